// round 1
// baseline (speedup 1.0000x reference)
#include <cuda_runtime.h>
#include <math.h>
#include <stdint.h>

// ---------------- problem constants ----------------
#define C_DIM   256
#define L_SEQ   16384
#define BATCH   4
#define NTOK    (BATCH * L_SEQ)     // 65536
#define HEADS   8
#define DHEAD   32
#define WIN     64
#define NWIN    (L_SEQ / WIN)       // 256
#define SHIFTV  32
#define LMASK   (L_SEQ - 1)

// ---------------- scratch (device globals; no allocation allowed) ----------------
__device__ float g_qkv[(size_t)NTOK * 768];    // [token, 3*C] (3,H,d) packing
__device__ float g_att[(size_t)NTOK * 256];    // attention out, flat [b,h,n,w,d]
__device__ float g_x2 [(size_t)NTOK * 256];    // proj output, un-shifted domain
__device__ float g_ln [(size_t)NTOK * 256];    // layernorm(x2)
__device__ float g_h  [(size_t)NTOK * 1024];   // mlp hidden

// ---------------- helpers ----------------
__device__ __forceinline__ float tf32r(float x) {
    unsigned u;
    asm("cvt.rna.tf32.f32 %0, %1;" : "=r"(u) : "f"(x));
    return __uint_as_float(u);
}

// =====================================================================
// Generic tf32 tensor-core GEMM:  out[M,NC] = A[M,K] @ W[K,NC] (+epilogue)
// BM=128, BN=64, BK=32, 256 threads (8 warps as 4x2, warp tile 32x32)
// MODE 0: A = x with shifted row gather       -> g_qkv           (no bias)
// MODE 1: A = g_att; +bias; reverse-shift row scatter -> g_x2
// MODE 2: A = g_ln;  +bias; exact GELU        -> g_h
// MODE 3: A = g_h;   +bias; +g_x2 residual    -> d_out
// =====================================================================
template<int MODE, int K, int NC>
__global__ __launch_bounds__(256)
void gemm_tf32_kernel(const float* __restrict__ Aext,
                      const float* __restrict__ W,
                      const float* __restrict__ bias,
                      float* __restrict__ outext)
{
    __shared__ float As[128][36];   // [m][k], pad to 36 (conflict-free frag loads)
    __shared__ float Bs[32][72];    // [k][n], pad to 72

    const float* __restrict__ A =
        (MODE == 0) ? Aext : (MODE == 1) ? g_att : (MODE == 2) ? g_ln : g_h;
    float* __restrict__ out =
        (MODE == 0) ? g_qkv : (MODE == 1) ? g_x2 : (MODE == 2) ? g_h : outext;

    const int tid  = threadIdx.x;
    const int bm   = blockIdx.y * 128;
    const int bn   = blockIdx.x * 64;
    const int lane = tid & 31;
    const int warp = tid >> 5;
    const int wm   = (warp >> 1) * 32;  // warp M offset (0..96)
    const int wn   = (warp & 1) * 32;   // warp N offset (0/32)

    float acc[2][4][4];
    #pragma unroll
    for (int i = 0; i < 2; i++)
        #pragma unroll
        for (int j = 0; j < 4; j++)
            #pragma unroll
            for (int r = 0; r < 4; r++) acc[i][j][r] = 0.0f;

    const int ar0 = tid >> 3;         // A load: row within pass (0..31)
    const int ac  = (tid & 7) * 4;    // A load: col (0..28)
    const int br0 = tid >> 4;         // B load: row within pass (0..15)
    const int bc  = (tid & 15) * 4;   // B load: col (0..60)

    // precompute gathered/plain A source rows for the 4 passes
    size_t asrc[4];
    #pragma unroll
    for (int p = 0; p < 4; p++) {
        int gr = bm + p * 32 + ar0;
        if (MODE == 0) {
            int b = gr >> 14, l = gr & LMASK;
            asrc[p] = (size_t)((b << 14) | ((l + SHIFTV) & LMASK));
        } else {
            asrc[p] = (size_t)gr;
        }
    }

    for (int kb = 0; kb < K; kb += 32) {
        // ---- load A tile (128x32) ----
        #pragma unroll
        for (int p = 0; p < 4; p++) {
            const float4 v = *(const float4*)(A + asrc[p] * K + kb + ac);
            const int r = p * 32 + ar0;
            As[r][ac + 0] = tf32r(v.x);
            As[r][ac + 1] = tf32r(v.y);
            As[r][ac + 2] = tf32r(v.z);
            As[r][ac + 3] = tf32r(v.w);
        }
        // ---- load B tile (32x64) ----
        #pragma unroll
        for (int p = 0; p < 2; p++) {
            const int r = p * 16 + br0;
            const float4 v = *(const float4*)(W + (size_t)(kb + r) * NC + bn + bc);
            Bs[r][bc + 0] = tf32r(v.x);
            Bs[r][bc + 1] = tf32r(v.y);
            Bs[r][bc + 2] = tf32r(v.z);
            Bs[r][bc + 3] = tf32r(v.w);
        }
        __syncthreads();

        #pragma unroll
        for (int ks = 0; ks < 4; ks++) {
            const int k0 = ks * 8;
            unsigned a[2][4], bf[4][2];
            #pragma unroll
            for (int mt = 0; mt < 2; mt++) {
                const int rm = wm + mt * 16 + (lane >> 2);
                a[mt][0] = __float_as_uint(As[rm    ][k0     + (lane & 3)]);
                a[mt][1] = __float_as_uint(As[rm + 8][k0     + (lane & 3)]);
                a[mt][2] = __float_as_uint(As[rm    ][k0 + 4 + (lane & 3)]);
                a[mt][3] = __float_as_uint(As[rm + 8][k0 + 4 + (lane & 3)]);
            }
            #pragma unroll
            for (int nt = 0; nt < 4; nt++) {
                const int cn = wn + nt * 8 + (lane >> 2);
                bf[nt][0] = __float_as_uint(Bs[k0     + (lane & 3)][cn]);
                bf[nt][1] = __float_as_uint(Bs[k0 + 4 + (lane & 3)][cn]);
            }
            #pragma unroll
            for (int mt = 0; mt < 2; mt++)
                #pragma unroll
                for (int nt = 0; nt < 4; nt++)
                    asm volatile(
                        "mma.sync.aligned.m16n8k8.row.col.f32.tf32.tf32.f32 "
                        "{%0,%1,%2,%3}, {%4,%5,%6,%7}, {%8,%9}, {%0,%1,%2,%3};"
                        : "+f"(acc[mt][nt][0]), "+f"(acc[mt][nt][1]),
                          "+f"(acc[mt][nt][2]), "+f"(acc[mt][nt][3])
                        : "r"(a[mt][0]), "r"(a[mt][1]), "r"(a[mt][2]), "r"(a[mt][3]),
                          "r"(bf[nt][0]), "r"(bf[nt][1]));
        }
        __syncthreads();
    }

    // ---- epilogue ----
    #pragma unroll
    for (int mt = 0; mt < 2; mt++)
        #pragma unroll
        for (int nt = 0; nt < 4; nt++)
            #pragma unroll
            for (int rg = 0; rg < 4; rg++) {
                const int r = bm + wm + mt * 16 + (lane >> 2) + ((rg >= 2) ? 8 : 0);
                const int c = bn + wn + nt * 8 + (lane & 3) * 2 + (rg & 1);
                float v = acc[mt][nt][rg];
                if (MODE != 0) v += bias[c];
                if (MODE == 2) v = 0.5f * v * (1.0f + erff(v * 0.70710678118654752f));
                if (MODE == 3) v += g_x2[(size_t)r * 256 + c];
                size_t orow = (size_t)r;
                if (MODE == 1) {
                    const int b = r >> 14, l = r & LMASK;
                    orow = (size_t)((b << 14) | ((l + SHIFTV) & LMASK));
                }
                out[orow * NC + c] = v;
            }
}

// =====================================================================
// Windowed attention: one block per (head, window, batch).
// Q,K,V are 64x32 fp32 tiles in smem (padded). Output written in flat
// [b,h,n,w,d] order so the proj GEMM reads it as the reference's reshape.
// =====================================================================
__global__ __launch_bounds__(256)
void attn_kernel(void)
{
    __shared__ float Qs[64][33];
    __shared__ float Ks[64][33];
    __shared__ float Vs[64][33];
    __shared__ float Ss[64][65];

    const int h = blockIdx.x, n = blockIdx.y, b = blockIdx.z;
    const int tid = threadIdx.x;
    const size_t tb = (size_t)b * L_SEQ + (size_t)n * WIN;

    // load q,k,v: 3 * 64 * 32 floats
    for (int idx = tid; idx < 3 * 2048; idx += 256) {
        const int arr = idx >> 11;
        const int rem = idx & 2047;
        const int row = rem >> 5, col = rem & 31;
        const float v = g_qkv[(tb + row) * 768 + (size_t)arr * 256 + h * 32 + col];
        float (*dst)[33] = (arr == 0) ? Qs : (arr == 1) ? Ks : Vs;
        dst[row][col] = v;
    }
    __syncthreads();

    const float scale = 0.17677669529663687f;  // 1/sqrt(32)
    for (int idx = tid; idx < 4096; idx += 256) {
        const int i = idx >> 6, j = idx & 63;
        float s = 0.0f;
        #pragma unroll
        for (int kk = 0; kk < 32; kk++) s += Qs[i][kk] * Ks[j][kk];
        Ss[i][j] = s * scale;
    }
    __syncthreads();

    if (tid < 64) {
        float m = -1e30f;
        #pragma unroll 8
        for (int j = 0; j < 64; j++) m = fmaxf(m, Ss[tid][j]);
        float sum = 0.0f;
        #pragma unroll 8
        for (int j = 0; j < 64; j++) {
            const float e = __expf(Ss[tid][j] - m);
            Ss[tid][j] = e;
            sum += e;
        }
        const float inv = 1.0f / sum;
        #pragma unroll 8
        for (int j = 0; j < 64; j++) Ss[tid][j] *= inv;
    }
    __syncthreads();

    float* dst = g_att + (((size_t)b * HEADS + h) * NWIN + n) * (WIN * DHEAD);
    for (int idx = tid; idx < 2048; idx += 256) {
        const int i = idx >> 5, dd = idx & 31;
        float s = 0.0f;
        #pragma unroll
        for (int j = 0; j < 64; j++) s += Ss[i][j] * Vs[j][dd];
        dst[i * 32 + dd] = s;
    }
}

// =====================================================================
// LayerNorm: one warp per token (8 tokens / 256-thread block)
// =====================================================================
__global__ __launch_bounds__(256)
void ln_kernel(const float* __restrict__ gamma, const float* __restrict__ beta)
{
    const int warp = threadIdx.x >> 5, lane = threadIdx.x & 31;
    const size_t t = (size_t)blockIdx.x * 8 + warp;
    const float* row = g_x2 + t * 256;
    const int c = lane * 4;

    const float4 v0 = *(const float4*)(row + c);
    const float4 v1 = *(const float4*)(row + 128 + c);
    float s = v0.x + v0.y + v0.z + v0.w + v1.x + v1.y + v1.z + v1.w;
    float q = v0.x * v0.x + v0.y * v0.y + v0.z * v0.z + v0.w * v0.w +
              v1.x * v1.x + v1.y * v1.y + v1.z * v1.z + v1.w * v1.w;
    #pragma unroll
    for (int o = 16; o; o >>= 1) {
        s += __shfl_xor_sync(0xFFFFFFFFu, s, o);
        q += __shfl_xor_sync(0xFFFFFFFFu, q, o);
    }
    const float mu   = s * (1.0f / 256.0f);
    const float var  = q * (1.0f / 256.0f) - mu * mu;
    const float rstd = rsqrtf(var + 1e-5f);

    float* o = g_ln + t * 256;
    const float4 g0 = *(const float4*)(gamma + c);
    const float4 b0 = *(const float4*)(beta + c);
    const float4 g1 = *(const float4*)(gamma + 128 + c);
    const float4 b1 = *(const float4*)(beta + 128 + c);
    float4 r0, r1;
    r0.x = (v0.x - mu) * rstd * g0.x + b0.x;
    r0.y = (v0.y - mu) * rstd * g0.y + b0.y;
    r0.z = (v0.z - mu) * rstd * g0.z + b0.z;
    r0.w = (v0.w - mu) * rstd * g0.w + b0.w;
    r1.x = (v1.x - mu) * rstd * g1.x + b1.x;
    r1.y = (v1.y - mu) * rstd * g1.y + b1.y;
    r1.z = (v1.z - mu) * rstd * g1.z + b1.z;
    r1.w = (v1.w - mu) * rstd * g1.w + b1.w;
    *(float4*)(o + c)       = r0;
    *(float4*)(o + 128 + c) = r1;
}

// =====================================================================
extern "C" void kernel_launch(void* const* d_in, const int* in_sizes, int n_in,
                              void* d_out, int out_size)
{
    const float* x      = (const float*)d_in[0];
    const float* w_qkv  = (const float*)d_in[1];
    const float* w_proj = (const float*)d_in[2];
    const float* b_proj = (const float*)d_in[3];
    const float* gamma2 = (const float*)d_in[4];
    const float* beta2  = (const float*)d_in[5];
    const float* w_mlp1 = (const float*)d_in[6];
    const float* b_mlp1 = (const float*)d_in[7];
    const float* w_mlp2 = (const float*)d_in[8];
    const float* b_mlp2 = (const float*)d_in[9];
    float* out = (float*)d_out;

    const int MB = NTOK / 128;  // 512

    // 1) QKV projection with shifted row gather
    gemm_tf32_kernel<0, 256, 768><<<dim3(768 / 64, MB), 256>>>(x, w_qkv, nullptr, nullptr);

    // 2) windowed attention
    attn_kernel<<<dim3(HEADS, NWIN, BATCH), 256>>>();

    // 3) output projection + bias + reverse-shift scatter -> x2
    gemm_tf32_kernel<1, 256, 256><<<dim3(256 / 64, MB), 256>>>(nullptr, w_proj, b_proj, nullptr);

    // 4) LayerNorm
    ln_kernel<<<NTOK / 8, 256>>>(gamma2, beta2);

    // 5) MLP1 + exact GELU
    gemm_tf32_kernel<2, 256, 1024><<<dim3(1024 / 64, MB), 256>>>(nullptr, w_mlp1, b_mlp1, nullptr);

    // 6) MLP2 + bias + residual -> d_out
    gemm_tf32_kernel<3, 1024, 256><<<dim3(256 / 64, MB), 256>>>(nullptr, w_mlp2, b_mlp2, out);
}

// round 2
// speedup vs baseline: 1.2762x; 1.2762x over previous
#include <cuda_runtime.h>
#include <math.h>
#include <stdint.h>

#define L_SEQ   16384
#define BATCH   4
#define NTOK    65536
#define HEADS   8
#define WIN     64
#define NWIN    256
#define SHIFTV  32
#define LMASK   (L_SEQ - 1)

// ---------------- scratch ----------------
__device__ float g_qkv[(size_t)NTOK * 768];
__device__ float g_att[(size_t)NTOK * 256];
__device__ float g_x2 [(size_t)NTOK * 256];
__device__ float g_ln [(size_t)NTOK * 256];
__device__ float g_h  [(size_t)NTOK * 1024];

// ---------------- helpers ----------------
__device__ __forceinline__ float tf32r(float x) {
    unsigned u; asm("cvt.rna.tf32.f32 %0, %1;" : "=r"(u) : "f"(x));
    return __uint_as_float(u);
}
__device__ __forceinline__ unsigned tf32u(float x) {
    unsigned u; asm("cvt.rna.tf32.f32 %0, %1;" : "=r"(u) : "f"(x));
    return u;
}
__device__ __forceinline__ void cpa16(float* smem, const float* gmem) {
    unsigned s = (unsigned)__cvta_generic_to_shared(smem);
    asm volatile("cp.async.cg.shared.global [%0], [%1], 16;" :: "r"(s), "l"(gmem) : "memory");
}
#define CP_COMMIT() asm volatile("cp.async.commit_group;" ::: "memory")
#define CP_WAIT0()  asm volatile("cp.async.wait_group 0;" ::: "memory")

#define MMA_TF32(D, A, B)                                                     \
    asm volatile(                                                             \
        "mma.sync.aligned.m16n8k8.row.col.f32.tf32.tf32.f32 "                 \
        "{%0,%1,%2,%3}, {%4,%5,%6,%7}, {%8,%9}, {%0,%1,%2,%3};"               \
        : "+f"((D)[0]), "+f"((D)[1]), "+f"((D)[2]), "+f"((D)[3])              \
        : "r"((A)[0]), "r"((A)[1]), "r"((A)[2]), "r"((A)[3]),                 \
          "r"((B)[0]), "r"((B)[1]))

// =====================================================================
// tf32 GEMM: out[M,NC] = A[M,K] @ W[K,NC] (+epilogue)
// BM=128, BN=128, BK=16, 2-stage cp.async, 256 thr, warps 4x2 (32x64 tile)
// MODE 0: A = x, shifted row gather -> g_qkv
// MODE 1: A = g_att; +bias; reverse-shift scatter -> g_x2
// MODE 2: A = g_ln;  +bias; exact GELU -> g_h
// MODE 3: A = g_h;   +bias; +g_x2 residual -> d_out
// =====================================================================
template<int MODE, int K, int NC>
__global__ __launch_bounds__(256, 2)
void gemm_tf32(const float* __restrict__ Aext, const float* __restrict__ W,
               const float* __restrict__ bias, float* __restrict__ outext)
{
    __shared__ float As[2][128][20];   // pad 20: (20*rm+k)%32 = (4rm+k) distinct
    __shared__ float Bs[2][16][136];   // pad 136: (8k+cn)%32 distinct

    const float* __restrict__ A =
        (MODE == 0) ? Aext : (MODE == 1) ? g_att : (MODE == 2) ? g_ln : g_h;
    float* __restrict__ out =
        (MODE == 0) ? g_qkv : (MODE == 1) ? g_x2 : (MODE == 2) ? g_h : outext;

    const int tid  = threadIdx.x;
    const int lane = tid & 31;
    const int warp = tid >> 5;
    const int bm   = blockIdx.y * 128;
    const int bn   = blockIdx.x * 128;
    const int wm   = (warp >> 1) * 32;
    const int wn   = (warp & 1) * 64;

    // A loader: rows r0=tid>>2 and r0+64, col (tid&3)*4
    const int ar0 = tid >> 2, akc = (tid & 3) * 4;
    size_t asrc0, asrc1;
    {
        const int g0 = bm + ar0, g1 = bm + ar0 + 64;
        if (MODE == 0) {
            asrc0 = (size_t)((g0 & ~LMASK) | ((g0 + SHIFTV) & LMASK));
            asrc1 = (size_t)((g1 & ~LMASK) | ((g1 + SHIFTV) & LMASK));
        } else { asrc0 = (size_t)g0; asrc1 = (size_t)g1; }
    }
    // B loader: rows br0 and br0+8, col (tid&31)*4
    const int br0 = tid >> 5, bcc = (tid & 31) * 4;

    float acc[2][8][4];
    #pragma unroll
    for (int i = 0; i < 2; i++)
        #pragma unroll
        for (int j = 0; j < 8; j++)
            #pragma unroll
            for (int r = 0; r < 4; r++) acc[i][j][r] = 0.0f;

    const int NKB = K / 16;

    // stage 0 prefetch
    {
        cpa16(&As[0][ar0][akc],      A + asrc0 * K + akc);
        cpa16(&As[0][ar0 + 64][akc], A + asrc1 * K + akc);
        cpa16(&Bs[0][br0][bcc],      W + (size_t)br0 * NC + bn + bcc);
        cpa16(&Bs[0][br0 + 8][bcc],  W + (size_t)(br0 + 8) * NC + bn + bcc);
        CP_COMMIT();
    }

    int buf = 0;
    for (int kb = 0; kb < NKB; kb++) {
        CP_WAIT0();
        __syncthreads();
        if (kb + 1 < NKB) {
            const int ko = (kb + 1) * 16;
            cpa16(&As[buf ^ 1][ar0][akc],      A + asrc0 * K + ko + akc);
            cpa16(&As[buf ^ 1][ar0 + 64][akc], A + asrc1 * K + ko + akc);
            cpa16(&Bs[buf ^ 1][br0][bcc],      W + (size_t)(ko + br0) * NC + bn + bcc);
            cpa16(&Bs[buf ^ 1][br0 + 8][bcc],  W + (size_t)(ko + br0 + 8) * NC + bn + bcc);
            CP_COMMIT();
        }
        #pragma unroll
        for (int ks = 0; ks < 2; ks++) {
            const int k0 = ks * 8;
            unsigned a[2][4], bq[8][2];
            #pragma unroll
            for (int mt = 0; mt < 2; mt++) {
                const int rm = wm + mt * 16 + (lane >> 2);
                a[mt][0] = tf32u(As[buf][rm    ][k0     + (lane & 3)]);
                a[mt][1] = tf32u(As[buf][rm + 8][k0     + (lane & 3)]);
                a[mt][2] = tf32u(As[buf][rm    ][k0 + 4 + (lane & 3)]);
                a[mt][3] = tf32u(As[buf][rm + 8][k0 + 4 + (lane & 3)]);
            }
            #pragma unroll
            for (int nt = 0; nt < 8; nt++) {
                const int cn = wn + nt * 8 + (lane >> 2);
                bq[nt][0] = tf32u(Bs[buf][k0     + (lane & 3)][cn]);
                bq[nt][1] = tf32u(Bs[buf][k0 + 4 + (lane & 3)][cn]);
            }
            #pragma unroll
            for (int mt = 0; mt < 2; mt++)
                #pragma unroll
                for (int nt = 0; nt < 8; nt++)
                    MMA_TF32(acc[mt][nt], a[mt], bq[nt]);
        }
        buf ^= 1;
    }

    // epilogue
    #pragma unroll
    for (int mt = 0; mt < 2; mt++)
        #pragma unroll
        for (int nt = 0; nt < 8; nt++) {
            const int c0 = bn + wn + nt * 8 + (lane & 3) * 2;
            float b0 = 0.0f, b1 = 0.0f;
            if (MODE != 0) { b0 = bias[c0]; b1 = bias[c0 + 1]; }
            #pragma unroll
            for (int rg = 0; rg < 4; rg++) {
                const int r = bm + wm + mt * 16 + (lane >> 2) + ((rg >= 2) ? 8 : 0);
                const int c = c0 + (rg & 1);
                float v = acc[mt][nt][rg] + ((rg & 1) ? b1 : b0);
                if (MODE == 2) v = 0.5f * v * (1.0f + erff(v * 0.70710678118654752f));
                if (MODE == 3) v += g_x2[(size_t)r * 256 + c];
                size_t orow = (size_t)r;
                if (MODE == 1) orow = (size_t)((r & ~LMASK) | ((r + SHIFTV) & LMASK));
                out[orow * (size_t)NC + c] = v;
            }
        }
}

// =====================================================================
// Windowed attention via tf32 mma. One block per (h, n, b), 256 threads.
// QK^T -> softmax (fp32) -> P.V. Output flat [b,h,n,w,d].
// =====================================================================
__global__ __launch_bounds__(256)
void attn_kernel(void)
{
    __shared__ float Qs[64][36];
    __shared__ float Ks[64][36];
    __shared__ float Vs[64][36];
    __shared__ float Ss[64][68];

    const int h = blockIdx.x, n = blockIdx.y, b = blockIdx.z;
    const int tid = threadIdx.x, lane = tid & 31, warp = tid >> 5;
    const size_t tb = (size_t)b * L_SEQ + (size_t)n * WIN;

    // load Q,K,V (64x32 each): 1536 float4, 6 per thread; tf32-round at store
    #pragma unroll
    for (int it = 0; it < 6; it++) {
        const int v = tid + it * 256;
        const int arr = v >> 9;
        const int rem = v & 511;
        const int row = rem >> 3, c4 = (rem & 7) * 4;
        const float4 t4 = *(const float4*)(g_qkv + (tb + row) * 768 + (size_t)arr * 256 + h * 32 + c4);
        float (*dst)[36] = (arr == 0) ? Qs : (arr == 1) ? Ks : Vs;
        dst[row][c4 + 0] = tf32r(t4.x);
        dst[row][c4 + 1] = tf32r(t4.y);
        dst[row][c4 + 2] = tf32r(t4.z);
        dst[row][c4 + 3] = tf32r(t4.w);
    }
    __syncthreads();

    const int wr = (warp & 3) * 16;      // warp row base (QK and AV)
    const int wc = (warp >> 2) * 32;     // warp col base (QK)

    // ---- S = Q K^T * scale ----
    {
        float acc[4][4];
        #pragma unroll
        for (int i = 0; i < 4; i++)
            #pragma unroll
            for (int r = 0; r < 4; r++) acc[i][r] = 0.0f;

        #pragma unroll
        for (int ks = 0; ks < 4; ks++) {
            const int k0 = ks * 8;
            unsigned a[4], bq[4][2];
            const int rm = wr + (lane >> 2);
            a[0] = __float_as_uint(Qs[rm    ][k0     + (lane & 3)]);
            a[1] = __float_as_uint(Qs[rm + 8][k0     + (lane & 3)]);
            a[2] = __float_as_uint(Qs[rm    ][k0 + 4 + (lane & 3)]);
            a[3] = __float_as_uint(Qs[rm + 8][k0 + 4 + (lane & 3)]);
            #pragma unroll
            for (int nt = 0; nt < 4; nt++) {
                const int cn = wc + nt * 8 + (lane >> 2);
                bq[nt][0] = __float_as_uint(Ks[cn][k0     + (lane & 3)]);
                bq[nt][1] = __float_as_uint(Ks[cn][k0 + 4 + (lane & 3)]);
            }
            #pragma unroll
            for (int nt = 0; nt < 4; nt++) MMA_TF32(acc[nt], a, bq[nt]);
        }
        const float scale = 0.17677669529663687f;
        #pragma unroll
        for (int nt = 0; nt < 4; nt++)
            #pragma unroll
            for (int rg = 0; rg < 4; rg++) {
                const int r = wr + (lane >> 2) + ((rg >= 2) ? 8 : 0);
                const int c = wc + nt * 8 + (lane & 3) * 2 + (rg & 1);
                Ss[r][c] = acc[nt][rg] * scale;
            }
    }
    __syncthreads();

    // ---- softmax (fp32, vectorized), final write tf32-rounded ----
    if (tid < 64) {
        float m = -1e30f;
        #pragma unroll
        for (int j4 = 0; j4 < 16; j4++) {
            const float4 s4 = *(const float4*)&Ss[tid][j4 * 4];
            m = fmaxf(m, fmaxf(fmaxf(s4.x, s4.y), fmaxf(s4.z, s4.w)));
        }
        float sum = 0.0f;
        #pragma unroll
        for (int j4 = 0; j4 < 16; j4++) {
            float4 s4 = *(float4*)&Ss[tid][j4 * 4];
            s4.x = __expf(s4.x - m); s4.y = __expf(s4.y - m);
            s4.z = __expf(s4.z - m); s4.w = __expf(s4.w - m);
            sum += s4.x + s4.y + s4.z + s4.w;
            *(float4*)&Ss[tid][j4 * 4] = s4;
        }
        const float inv = 1.0f / sum;
        #pragma unroll
        for (int j4 = 0; j4 < 16; j4++) {
            float4 s4 = *(float4*)&Ss[tid][j4 * 4];
            s4.x = tf32r(s4.x * inv); s4.y = tf32r(s4.y * inv);
            s4.z = tf32r(s4.z * inv); s4.w = tf32r(s4.w * inv);
            *(float4*)&Ss[tid][j4 * 4] = s4;
        }
    }
    __syncthreads();

    // ---- O = P V ----
    {
        const int wc2 = (warp >> 2) * 16;
        float acc[2][4];
        #pragma unroll
        for (int i = 0; i < 2; i++)
            #pragma unroll
            for (int r = 0; r < 4; r++) acc[i][r] = 0.0f;

        #pragma unroll
        for (int ks = 0; ks < 8; ks++) {
            const int k0 = ks * 8;
            unsigned a[4], bq[2][2];
            const int rm = wr + (lane >> 2);
            a[0] = __float_as_uint(Ss[rm    ][k0     + (lane & 3)]);
            a[1] = __float_as_uint(Ss[rm + 8][k0     + (lane & 3)]);
            a[2] = __float_as_uint(Ss[rm    ][k0 + 4 + (lane & 3)]);
            a[3] = __float_as_uint(Ss[rm + 8][k0 + 4 + (lane & 3)]);
            #pragma unroll
            for (int nt = 0; nt < 2; nt++) {
                const int cn = wc2 + nt * 8 + (lane >> 2);
                bq[nt][0] = __float_as_uint(Vs[k0     + (lane & 3)][cn]);
                bq[nt][1] = __float_as_uint(Vs[k0 + 4 + (lane & 3)][cn]);
            }
            #pragma unroll
            for (int nt = 0; nt < 2; nt++) MMA_TF32(acc[nt], a, bq[nt]);
        }
        float* dst = g_att + (((size_t)b * HEADS + h) * NWIN + n) * 2048;
        #pragma unroll
        for (int nt = 0; nt < 2; nt++)
            #pragma unroll
            for (int rg = 0; rg < 4; rg++) {
                const int r = wr + (lane >> 2) + ((rg >= 2) ? 8 : 0);
                const int c = wc2 + nt * 8 + (lane & 3) * 2 + (rg & 1);
                dst[r * 32 + c] = acc[nt][rg];
            }
    }
}

// =====================================================================
// LayerNorm: one warp per token
// =====================================================================
__global__ __launch_bounds__(256)
void ln_kernel(const float* __restrict__ gamma, const float* __restrict__ beta)
{
    const int warp = threadIdx.x >> 5, lane = threadIdx.x & 31;
    const size_t t = (size_t)blockIdx.x * 8 + warp;
    const float* row = g_x2 + t * 256;
    const int c = lane * 4;

    const float4 v0 = *(const float4*)(row + c);
    const float4 v1 = *(const float4*)(row + 128 + c);
    float s = v0.x + v0.y + v0.z + v0.w + v1.x + v1.y + v1.z + v1.w;
    float q = v0.x * v0.x + v0.y * v0.y + v0.z * v0.z + v0.w * v0.w +
              v1.x * v1.x + v1.y * v1.y + v1.z * v1.z + v1.w * v1.w;
    #pragma unroll
    for (int o = 16; o; o >>= 1) {
        s += __shfl_xor_sync(0xFFFFFFFFu, s, o);
        q += __shfl_xor_sync(0xFFFFFFFFu, q, o);
    }
    const float mu   = s * (1.0f / 256.0f);
    const float var  = q * (1.0f / 256.0f) - mu * mu;
    const float rstd = rsqrtf(var + 1e-5f);

    float* o = g_ln + t * 256;
    const float4 g0 = *(const float4*)(gamma + c);
    const float4 b0 = *(const float4*)(beta + c);
    const float4 g1 = *(const float4*)(gamma + 128 + c);
    const float4 b1 = *(const float4*)(beta + 128 + c);
    float4 r0, r1;
    r0.x = (v0.x - mu) * rstd * g0.x + b0.x;
    r0.y = (v0.y - mu) * rstd * g0.y + b0.y;
    r0.z = (v0.z - mu) * rstd * g0.z + b0.z;
    r0.w = (v0.w - mu) * rstd * g0.w + b0.w;
    r1.x = (v1.x - mu) * rstd * g1.x + b1.x;
    r1.y = (v1.y - mu) * rstd * g1.y + b1.y;
    r1.z = (v1.z - mu) * rstd * g1.z + b1.z;
    r1.w = (v1.w - mu) * rstd * g1.w + b1.w;
    *(float4*)(o + c)       = r0;
    *(float4*)(o + 128 + c) = r1;
}

// =====================================================================
extern "C" void kernel_launch(void* const* d_in, const int* in_sizes, int n_in,
                              void* d_out, int out_size)
{
    const float* x      = (const float*)d_in[0];
    const float* w_qkv  = (const float*)d_in[1];
    const float* w_proj = (const float*)d_in[2];
    const float* b_proj = (const float*)d_in[3];
    const float* gamma2 = (const float*)d_in[4];
    const float* beta2  = (const float*)d_in[5];
    const float* w_mlp1 = (const float*)d_in[6];
    const float* b_mlp1 = (const float*)d_in[7];
    const float* w_mlp2 = (const float*)d_in[8];
    const float* b_mlp2 = (const float*)d_in[9];
    float* out = (float*)d_out;

    gemm_tf32<0, 256, 768><<<dim3(6, 512), 256>>>(x, w_qkv, nullptr, nullptr);
    attn_kernel<<<dim3(HEADS, NWIN, BATCH), 256>>>();
    gemm_tf32<1, 256, 256><<<dim3(2, 512), 256>>>(nullptr, w_proj, b_proj, nullptr);
    ln_kernel<<<NTOK / 8, 256>>>(gamma2, beta2);
    gemm_tf32<2, 256, 1024><<<dim3(8, 512), 256>>>(nullptr, w_mlp1, b_mlp1, nullptr);
    gemm_tf32<3, 1024, 256><<<dim3(2, 512), 256>>>(nullptr, w_mlp2, b_mlp2, out);
}